// round 7
// baseline (speedup 1.0000x reference)
#include <cuda_runtime.h>
#include <math.h>

// Problem dims
#define NB 2048
#define NT 512
#define NP 8
#define NL 64
#define NH 180
#define NH3 540
#define KIN (NP+NL)     // 72
#define KO1 (NH+NL)     // 244
#define KPAD 24

#define RT 16           // batch rows per CTA
#define NCTA (NB/RT)    // 128
#define THREADS 512

typedef unsigned long long u64;

// -------- K-major (transposed) weights, padded k-rows for deep prefetch ----
__device__ float g_WTin[(KIN+KPAD)*NH];
__device__ float g_WThp[(NL+KPAD)*NH];
__device__ float g_WTih[(NH+KPAD)*NH3];
__device__ float g_WThh[(NH+KPAD)*NH3];
__device__ float g_WTo1[(KO1+KPAD)*NH];
__device__ float g_WTo2[(NH+KPAD)*NL];

// grid barrier state
__device__ unsigned g_cnt = 0;
__device__ volatile unsigned g_rel = 0;

__device__ __forceinline__ u64 ff2(u64 a, u64 b, u64 c) {
    u64 d;
    asm("fma.rn.f32x2 %0, %1, %2, %3;" : "=l"(d) : "l"(a), "l"(b), "l"(c));
    return d;
}
__device__ __forceinline__ u64 dup2(float w) {
    u64 d;
    asm("mov.b64 %0, {%1, %1};" : "=l"(d) : "f"(w), "f"(w));
    return d;
}
__device__ __forceinline__ void unpk(u64 p, float& lo, float& hi) {
    asm("mov.b64 {%0, %1}, %2;" : "=f"(lo), "=f"(hi) : "l"(p));
}
__device__ __forceinline__ void fq(const float* p, u64& a, u64& b) {
    double2 q = *reinterpret_cast<const double2*>(p);
    a = __double_as_longlong(q.x);
    b = __double_as_longlong(q.y);
}
__device__ __forceinline__ u64 f8(const float* p) {
    return __double_as_longlong(*reinterpret_cast<const double*>(p));
}
__device__ __forceinline__ float gelu_f(float x) {
    return 0.5f * x * (1.0f + erff(x * 0.7071067811865476f));
}
__device__ __forceinline__ float sigmoid_f(float x) {
    return 1.0f / (1.0f + expf(-x));
}

// ---- weight fetch helper ----
template<int O>
__device__ __forceinline__ void lw4s(const float* Wc, int k, float (&w)[4]) {
#pragma unroll
    for (int i = 0; i < 4; i++)
        w[i] = Wc[(size_t)(k + i) * O];
}

// ---- compute chunk: 4 k's, single col, 8 row-pairs ----
template<int STRIDE>
__device__ __forceinline__ void cc_sing(const float* sATk, const float (&w)[4],
                                        u64 (&acc)[8]) {
#pragma unroll
    for (int kk = 0; kk < 4; kk++) {
        u64 a[8];
        const float* ap = sATk + kk * STRIDE;
        fq(ap + 0,  a[0], a[1]);
        fq(ap + 4,  a[2], a[3]);
        fq(ap + 8,  a[4], a[5]);
        fq(ap + 12, a[6], a[7]);
        u64 wp = dup2(w[kk]);
#pragma unroll
        for (int rp = 0; rp < 8; rp++) acc[rp] = ff2(a[rp], wp, acc[rp]);
    }
}

// ---- pipelined single-col GEMM over runtime [k0,k1), (k1-k0)%4==0 ----
template<int O, int STRIDE>
__device__ __forceinline__ void gemm_sing(const float* __restrict__ sAT,
                                          const float* __restrict__ W,
                                          int col, int k0, int k1, u64 (&acc)[8]) {
#pragma unroll
    for (int rp = 0; rp < 8; rp++) acc[rp] = 0ull;
    const float* Wc = W + col;
    float w0[4], w1[4], w2[4], w3[4];
    lw4s<O>(Wc, k0, w0);
    lw4s<O>(Wc, k0 + 4, w1);
    lw4s<O>(Wc, k0 + 8, w2);
    int k = k0;
#pragma unroll 1
    for (; k + 16 <= k1; k += 16) {
        lw4s<O>(Wc, k + 12, w3); cc_sing<STRIDE>(sAT + k * STRIDE, w0, acc);
        lw4s<O>(Wc, k + 16, w0); cc_sing<STRIDE>(sAT + (k + 4) * STRIDE, w1, acc);
        lw4s<O>(Wc, k + 20, w1); cc_sing<STRIDE>(sAT + (k + 8) * STRIDE, w2, acc);
        lw4s<O>(Wc, k + 24, w2); cc_sing<STRIDE>(sAT + (k + 12) * STRIDE, w3, acc);
    }
    if (k1 - k >= 4)  cc_sing<STRIDE>(sAT + k * STRIDE, w0, acc);
    if (k1 - k >= 8)  cc_sing<STRIDE>(sAT + (k + 4) * STRIDE, w1, acc);
    if (k1 - k >= 12) cc_sing<STRIDE>(sAT + (k + 8) * STRIDE, w2, acc);
}

// SMEM layout (floats)
#define OFF_INT  0                        // sInT [72][20]
#define OFF_XT   (OFF_INT + 72*20)        // sXT  [180][20]
#define OFF_HT   (OFF_XT + 180*20)        // sHT  [180][20]
#define OFF_HCT  (OFF_HT + 180*20)        // sHCT [244][20]
#define OFF_OT   (OFF_HCT + 244*20)       // sOT  [180][20]
#define OFF_GH   (OFF_OT + 180*20)        // ghT  [652][17]
#define OFF_GI   (OFF_GH + 652*17)        // giT  [680][17] (also xP[500][17], o1P[360][17])
#define OFF_CUR  (OFF_GI + 680*17)        // sCur [16][64]
#define SMEM_FLOATS (OFF_CUR + 16*64)
#define SMEM_BYTES  (SMEM_FLOATS * 4)

__device__ __forceinline__ void tr_slice(const float* src, float* dst, int O, int K,
                                         int start, int stride) {
    for (int i = start; i < O * K; i += stride) {
        int o = i / K, k = i - o * K;
        dst[k * O + o] = src[i];
    }
}

__global__ __launch_bounds__(THREADS, 1)
void rnn_kernel(const float* __restrict__ phys,
                const float* __restrict__ latents,
                const float* __restrict__ W_in, const float* __restrict__ b_in,
                const float* __restrict__ W_hp, const float* __restrict__ b_hp,
                const float* __restrict__ W_ih, const float* __restrict__ b_ih,
                const float* __restrict__ W_hh, const float* __restrict__ b_hh,
                const float* __restrict__ W_o1, const float* __restrict__ b_o1,
                const float* __restrict__ W_o2, const float* __restrict__ b_o2,
                float* __restrict__ out)
{
    extern __shared__ float sm[];
    float* sInT = sm + OFF_INT;
    float* sXT  = sm + OFF_XT;
    float* sHT  = sm + OFF_HT;
    float* sHCT = sm + OFF_HCT;
    float* sOT  = sm + OFF_OT;
    float* ghT  = sm + OFF_GH;
    float* giT  = sm + OFF_GI;
    float* sCur = sm + OFF_CUR;

    const int tid  = threadIdx.x;
    const int b0   = blockIdx.x * RT;

    // ---------- in-kernel weight transpose + grid barrier ----------
    {
        int start = blockIdx.x * THREADS + tid;
        int stride = NCTA * THREADS;
        tr_slice(W_in, g_WTin, NH, KIN, start, stride);
        tr_slice(W_hp, g_WThp, NH, NL, start, stride);
        tr_slice(W_ih, g_WTih, NH3, NH, start, stride);
        tr_slice(W_hh, g_WThh, NH3, NH, start, stride);
        tr_slice(W_o1, g_WTo1, NH, KO1, start, stride);
        tr_slice(W_o2, g_WTo2, NL, NH, start, stride);
    }
    __syncthreads();
    if (tid == 0) {
        unsigned p = g_rel;
        __threadfence();
        unsigned a = atomicAdd(&g_cnt, 1);
        if (a == NCTA - 1) {
            g_cnt = 0;
            __threadfence();
            g_rel = p + 1;
        } else {
            while (g_rel == p) { }
        }
        __threadfence();
    }
    __syncthreads();

    // ---------- prologue: cur = latents; sInT = [phys0 | cur]; h0 ----------
    for (int i = tid; i < RT * NL; i += THREADS) {
        int r = i & 15, l = i >> 4;
        float v = latents[(size_t)(b0 + r) * NL + l];
        sCur[r * NL + l] = v;
        sInT[(NP + l) * 20 + r] = v;
    }
    if (tid < RT * NP) {
        int r = tid >> 3, p = tid & 7;
        sInT[p * 20 + r] = phys[((size_t)(b0 + r) * NT + 0) * NP + p];
    }
    __syncthreads();
    if (tid < NH) {
        float acc[16];
#pragma unroll
        for (int r = 0; r < 16; r++) acc[r] = 0.0f;
        for (int k = 0; k < NL; k++) {
            float w = g_WThp[k * NH + tid];
#pragma unroll
            for (int r = 0; r < 16; r++)
                acc[r] = fmaf(sCur[r * NL + k], w, acc[r]);
        }
        float bb = b_hp[tid];
#pragma unroll
        for (int r = 0; r < 16; r++) sHT[tid * 20 + r] = acc[r] + bb;
    }
    __syncthreads();

    // ---------- main time loop ----------
#pragma unroll 1
    for (int t = 0; t < NT; t++) {
        // ===== Phase A: gh cols 0..511 (full K) + 500 extra 36-k jobs =====
        {
            u64 acc[8];
            gemm_sing<NH3, 20>(sHT, g_WThh, tid, 0, NH, acc);
            float bb = b_hh[tid];
#pragma unroll
            for (int rp = 0; rp < 8; rp++) {
                float lo, hi;
                unpk(acc[rp], lo, hi);
                ghT[tid * 17 + 2 * rp]     = lo + bb;
                ghT[tid * 17 + 2 * rp + 1] = hi + bb;
            }
        }
        if (tid < 500) {
            u64 acc[8];
            if (tid < 360) {
                // x-gemm halves: col = tid/2, K-half = tid%2 (36 k each)
                int col = tid >> 1, half = tid & 1;
                gemm_sing<NH, 20>(sInT, g_WTin, col, half * 36, half * 36 + 36, acc);
#pragma unroll
                for (int rp = 0; rp < 8; rp++) {
                    float lo, hi;
                    unpk(acc[rp], lo, hi);
                    giT[tid * 17 + 2 * rp]     = lo;   // xP partial
                    giT[tid * 17 + 2 * rp + 1] = hi;
                }
            } else {
                // gh tail cols 512..539, 5 K-fifths of 36
                int u = tid - 360;
                int s = u / 5, seg = u - 5 * s;
                int col = 512 + s;
                gemm_sing<NH3, 20>(sHT, g_WThh, col, seg * 36, seg * 36 + 36, acc);
                int dcol = (seg == 0) ? col : (540 + s * 4 + (seg - 1));
                float bb = (seg == 0) ? b_hh[col] : 0.0f;
#pragma unroll
                for (int rp = 0; rp < 8; rp++) {
                    float lo, hi;
                    unpk(acc[rp], lo, hi);
                    ghT[dcol * 17 + 2 * rp]     = lo + bb;
                    ghT[dcol * 17 + 2 * rp + 1] = hi + bb;
                }
            }
        }
        __syncthreads();

        // ===== x-reduce: sXT = gelu(xP0 + xP1 + b_in) =====
        for (int i = tid; i < RT * NH; i += THREADS) {
            int r = i & 15, c = i >> 4;
            float v = giT[(2 * c) * 17 + r] + giT[(2 * c + 1) * 17 + r] + b_in[c];
            sXT[c * 20 + r] = gelu_f(v);
        }
        __syncthreads();

        // ===== Phase B: gi cols 0..511 (full K) + tail fifths on threads 0..139 =====
        {
            u64 acc[8];
            gemm_sing<NH3, 20>(sXT, g_WTih, tid, 0, NH, acc);
            float bb = b_ih[tid];
#pragma unroll
            for (int rp = 0; rp < 8; rp++) {
                float lo, hi;
                unpk(acc[rp], lo, hi);
                giT[tid * 17 + 2 * rp]     = lo + bb;
                giT[tid * 17 + 2 * rp + 1] = hi + bb;
            }
        }
        if (tid < 140) {
            int s = tid / 5, seg = tid - 5 * s;
            int col = 512 + s;
            u64 acc[8];
            gemm_sing<NH3, 20>(sXT, g_WTih, col, seg * 36, seg * 36 + 36, acc);
            int dcol = (seg == 0) ? col : (540 + s * 4 + (seg - 1));
            float bb = (seg == 0) ? b_ih[col] : 0.0f;
#pragma unroll
            for (int rp = 0; rp < 8; rp++) {
                float lo, hi;
                unpk(acc[rp], lo, hi);
                giT[dcol * 17 + 2 * rp]     = lo + bb;
                giT[dcol * 17 + 2 * rp + 1] = hi + bb;
            }
        }
        __syncthreads();

        // ===== Phase C: gates -> h_new; build sHT, sHCT =====
        for (int i = tid; i < RT * NH; i += THREADS) {
            int r = i & 15, j = i >> 4;
            float gir = giT[j * 17 + r];
            float giz = giT[(NH + j) * 17 + r];
            float gin = giT[(2 * NH + j) * 17 + r];
            float ghr = ghT[j * 17 + r];
            float ghz = ghT[(NH + j) * 17 + r];
            float ghn = ghT[(2 * NH + j) * 17 + r];
            if (j >= 152) {
                int s = j - 152;
                gin += giT[(540 + 4 * s) * 17 + r] + giT[(541 + 4 * s) * 17 + r]
                     + giT[(542 + 4 * s) * 17 + r] + giT[(543 + 4 * s) * 17 + r];
                ghn += ghT[(540 + 4 * s) * 17 + r] + ghT[(541 + 4 * s) * 17 + r]
                     + ghT[(542 + 4 * s) * 17 + r] + ghT[(543 + 4 * s) * 17 + r];
            }
            float rr = sigmoid_f(gir + ghr);
            float zz = sigmoid_f(giz + ghz);
            float nn = tanhf(gin + rr * ghn);
            float hn = (1.0f - zz) * nn + zz * sHT[j * 20 + r];
            sHT[j * 20 + r]  = hn;
            sHCT[j * 20 + r] = hn;
        }
        for (int i = tid; i < RT * NL; i += THREADS) {
            int r = i & 15, l = i >> 4;
            sHCT[(NH + l) * 20 + r] = sCur[r * NL + l];
        }
        __syncthreads();

        // ===== Phase D: o1 partials (2 K-segments x 180 cols = 360 jobs) =====
        if (tid < 360) {
            int col = tid % 180;
            int seg = tid / 180;
            int k0 = seg ? 124 : 0;
            int k1 = seg ? KO1 : 124;
            u64 acc[8];
            gemm_sing<NH, 20>(sHCT, g_WTo1, col, k0, k1, acc);
#pragma unroll
            for (int rp = 0; rp < 8; rp++) {
                float lo, hi;
                unpk(acc[rp], lo, hi);
                giT[(seg * 180 + col) * 17 + 2 * rp]     = lo;
                giT[(seg * 180 + col) * 17 + 2 * rp + 1] = hi;
            }
        }
        __syncthreads();

        // ===== Phase D2: reduce + bias + gelu -> sOT =====
        for (int i = tid; i < RT * NH; i += THREADS) {
            int r = i & 15, c = i >> 4;
            float v = giT[c * 17 + r] + giT[(180 + c) * 17 + r] + b_o1[c];
            sOT[c * 20 + r] = gelu_f(v);
        }
        __syncthreads();

        // ===== Phase E: delta = o @ W_o2^T (64 cols x 8 row-pairs = 512 jobs) =====
        {
            int col = tid & 63;
            int rp  = tid >> 6;     // row pair: rows 2rp, 2rp+1
            const float* Wc = g_WTo2 + col;
            const float* A0 = sOT + 2 * rp;
            u64 acc = 0ull;
            float w0[4], w1[4], w2[4], w3[4];
            lw4s<NL>(Wc, 0, w0);
            lw4s<NL>(Wc, 4, w1);
            lw4s<NL>(Wc, 8, w2);
            int k = 0;
#pragma unroll 1
            for (; k + 16 <= NH; k += 16) {
                lw4s<NL>(Wc, k + 12, w3);
#pragma unroll
                for (int kk = 0; kk < 4; kk++)
                    acc = ff2(f8(A0 + (k + kk) * 20), dup2(w0[kk]), acc);
                lw4s<NL>(Wc, k + 16, w0);
#pragma unroll
                for (int kk = 0; kk < 4; kk++)
                    acc = ff2(f8(A0 + (k + 4 + kk) * 20), dup2(w1[kk]), acc);
                lw4s<NL>(Wc, k + 20, w1);
#pragma unroll
                for (int kk = 0; kk < 4; kk++)
                    acc = ff2(f8(A0 + (k + 8 + kk) * 20), dup2(w2[kk]), acc);
                lw4s<NL>(Wc, k + 24, w2);
#pragma unroll
                for (int kk = 0; kk < 4; kk++)
                    acc = ff2(f8(A0 + (k + 12 + kk) * 20), dup2(w3[kk]), acc);
            }
            if (NH - k >= 4) {
#pragma unroll
                for (int kk = 0; kk < 4; kk++)
                    acc = ff2(f8(A0 + (k + kk) * 20), dup2(w0[kk]), acc);
            }
            if (NH - k >= 8) {
#pragma unroll
                for (int kk = 0; kk < 4; kk++)
                    acc = ff2(f8(A0 + (k + 4 + kk) * 20), dup2(w1[kk]), acc);
            }
            if (NH - k >= 12) {
#pragma unroll
                for (int kk = 0; kk < 4; kk++)
                    acc = ff2(f8(A0 + (k + 8 + kk) * 20), dup2(w2[kk]), acc);
            }
            float v0, v1;
            unpk(acc, v0, v1);
            float bb = b_o2[col];
            int row0 = 2 * rp;
            float c0 = sCur[row0 * NL + col] + v0 + bb;
            c0 = fminf(fmaxf(c0, 0.0f), 1.0f);
            sCur[row0 * NL + col] = c0;
            sInT[(NP + col) * 20 + row0] = c0;
            out[((size_t)(b0 + row0) * NT + t) * NL + col] = c0;
            int row1 = row0 + 1;
            float c1 = sCur[row1 * NL + col] + v1 + bb;
            c1 = fminf(fmaxf(c1, 0.0f), 1.0f);
            sCur[row1 * NL + col] = c1;
            sInT[(NP + col) * 20 + row1] = c1;
            out[((size_t)(b0 + row1) * NT + t) * NL + col] = c1;
        }
        if (tid < RT * NP && t + 1 < NT) {
            int r = tid >> 3, p = tid & 7;
            sInT[p * 20 + r] = phys[((size_t)(b0 + r) * NT + t + 1) * NP + p];
        }
        __syncthreads();
    }
}

extern "C" void kernel_launch(void* const* d_in, const int* in_sizes, int n_in,
                              void* d_out, int out_size)
{
    const float* phys    = (const float*)d_in[0];
    const float* latents = (const float*)d_in[1];
    const float* W_in    = (const float*)d_in[2];
    const float* b_in    = (const float*)d_in[3];
    const float* W_hp    = (const float*)d_in[4];
    const float* b_hp    = (const float*)d_in[5];
    const float* W_ih    = (const float*)d_in[6];
    const float* b_ih    = (const float*)d_in[7];
    const float* W_hh    = (const float*)d_in[8];
    const float* b_hh    = (const float*)d_in[9];
    const float* W_o1    = (const float*)d_in[10];
    const float* b_o1    = (const float*)d_in[11];
    const float* W_o2    = (const float*)d_in[12];
    const float* b_o2    = (const float*)d_in[13];
    float* out = (float*)d_out;

    cudaFuncSetAttribute(rnn_kernel,
                         cudaFuncAttributeMaxDynamicSharedMemorySize, SMEM_BYTES);
    rnn_kernel<<<NCTA, THREADS, SMEM_BYTES>>>(phys, latents,
                                              W_in, b_in, W_hp, b_hp,
                                              W_ih, b_ih, W_hh, b_hh,
                                              W_o1, b_o1, W_o2, b_o2, out);
}

// round 8
// speedup vs baseline: 1.3422x; 1.3422x over previous
#include <cuda_runtime.h>
#include <math.h>

// Problem dims
#define NB 2048
#define NT 512
#define NP 8
#define NL 64
#define NH 180
#define NH3 540
#define KIN (NP+NL)     // 72
#define KO1 (NH+NL)     // 244
#define KPAD 28

#define RT 16           // batch rows per CTA
#define NCTA (NB/RT)    // 128
#define THREADS 256

typedef unsigned long long u64;

// -------- K-major (transposed) weights, padded k-rows for deep prefetch ----
__device__ __align__(16) float g_WTin[(KIN+KPAD)*NH];
__device__ __align__(16) float g_WThp[(NL+KPAD)*NH];
__device__ __align__(16) float g_WTih[(NH+KPAD)*NH3];
__device__ __align__(16) float g_WThh[(NH+KPAD)*NH3];
__device__ __align__(16) float g_WTo1[(KO1+KPAD)*NH];
__device__ __align__(16) float g_WTo2[(NH+KPAD)*NL];

// grid barrier state
__device__ unsigned g_cnt = 0;
__device__ volatile unsigned g_rel = 0;

__device__ __forceinline__ u64 ff2(u64 a, u64 b, u64 c) {
    u64 d;
    asm("fma.rn.f32x2 %0, %1, %2, %3;" : "=l"(d) : "l"(a), "l"(b), "l"(c));
    return d;
}
__device__ __forceinline__ u64 ad2(u64 a, u64 b) {
    u64 d;
    asm("add.rn.f32x2 %0, %1, %2;" : "=l"(d) : "l"(a), "l"(b));
    return d;
}
__device__ __forceinline__ u64 dup2(float w) {
    u64 d;
    asm("mov.b64 %0, {%1, %1};" : "=l"(d) : "f"(w), "f"(w));
    return d;
}
__device__ __forceinline__ void unpk(u64 p, float& lo, float& hi) {
    asm("mov.b64 {%0, %1}, %2;" : "=f"(lo), "=f"(hi) : "l"(p));
}
__device__ __forceinline__ void fq(const float* p, u64& a, u64& b) {
    double2 q = *reinterpret_cast<const double2*>(p);
    a = __double_as_longlong(q.x);
    b = __double_as_longlong(q.y);
}
__device__ __forceinline__ float gelu_f(float x) {
    return 0.5f * x * (1.0f + erff(x * 0.7071067811865476f));
}
__device__ __forceinline__ float sigmoid_f(float x) {
    return 1.0f / (1.0f + expf(-x));
}

// ---- weight fetch: 4 k-rows x NC cols ----
template<int O, int NC>
__device__ __forceinline__ void lw(const float* Wc, int k, float (&w)[4][NC]) {
#pragma unroll
    for (int i = 0; i < 4; i++) {
        if constexpr (NC == 4) {
            float4 v = *reinterpret_cast<const float4*>(Wc + (size_t)(k + i) * O);
            w[i][0] = v.x; w[i][1] = v.y; w[i][2] = v.z; w[i][3] = v.w;
        } else if constexpr (NC == 2) {
            float2 v = *reinterpret_cast<const float2*>(Wc + (size_t)(k + i) * O);
            w[i][0] = v.x; w[i][1] = v.y;
        } else {
            w[i][0] = Wc[(size_t)(k + i) * O];
        }
    }
}

// ---- compute chunk: 4 k's, NC cols, 8 rows (4 row-pairs) ----
template<int STRIDE, int NC>
__device__ __forceinline__ void cc8(const float* sATk, int rb,
                                    const float (&w)[4][NC], u64 (&acc)[NC][4]) {
#pragma unroll
    for (int kk = 0; kk < 4; kk++) {
        u64 a[4];
        const float* ap = sATk + kk * STRIDE + rb;
        fq(ap,     a[0], a[1]);
        fq(ap + 4, a[2], a[3]);
#pragma unroll
        for (int c = 0; c < NC; c++) {
            u64 wp = dup2(w[kk][c]);
#pragma unroll
            for (int rp = 0; rp < 4; rp++)
                acc[c][rp] = ff2(a[rp], wp, acc[c][rp]);
        }
    }
}

// ---- pipelined GEMM: NC cols starting col0, rows rb..rb+7, k in [k0,k1) (%4==0) ----
template<int O, int NC, int STRIDE>
__device__ __forceinline__ void gemm8(const float* __restrict__ sAT, int rb,
                                      const float* __restrict__ W, int col0,
                                      int k0, int k1, u64 (&acc)[NC][4]) {
#pragma unroll
    for (int c = 0; c < NC; c++)
#pragma unroll
        for (int rp = 0; rp < 4; rp++) acc[c][rp] = 0ull;
    const float* Wc = W + col0;
    float w0[4][NC], w1[4][NC], w2[4][NC], w3[4][NC];
    lw<O, NC>(Wc, k0, w0);
    lw<O, NC>(Wc, k0 + 4, w1);
    lw<O, NC>(Wc, k0 + 8, w2);
    int k = k0;
#pragma unroll 1
    for (; k + 16 <= k1; k += 16) {
        lw<O, NC>(Wc, k + 12, w3); cc8<STRIDE, NC>(sAT + k * STRIDE, rb, w0, acc);
        lw<O, NC>(Wc, k + 16, w0); cc8<STRIDE, NC>(sAT + (k + 4) * STRIDE, rb, w1, acc);
        lw<O, NC>(Wc, k + 20, w1); cc8<STRIDE, NC>(sAT + (k + 8) * STRIDE, rb, w2, acc);
        lw<O, NC>(Wc, k + 24, w2); cc8<STRIDE, NC>(sAT + (k + 12) * STRIDE, rb, w3, acc);
    }
    if (k1 - k >= 4)  cc8<STRIDE, NC>(sAT + k * STRIDE, rb, w0, acc);
    if (k1 - k >= 8)  cc8<STRIDE, NC>(sAT + (k + 4) * STRIDE, rb, w1, acc);
    if (k1 - k >= 12) cc8<STRIDE, NC>(sAT + (k + 8) * STRIDE, rb, w2, acc);
}

// SMEM layout (floats)
#define OFF_INT  0                        // sInT [72][20]
#define OFF_XT   (OFF_INT + 72*20)        // sXT  [180][20]
#define OFF_HT   (OFF_XT + 180*20)        // sHT  [180][20]
#define OFF_HCT  (OFF_HT + 180*20)        // sHCT [244][20]
#define OFF_OT   (OFF_HCT + 244*20)       // sOT  [180][20]
#define OFF_GH   (OFF_OT + 180*20)        // ghT  [568][18] (also o2 partials [128][18])
#define OFF_GI   (OFF_GH + 568*18)        // giT  [568][18] (also o1 partials [360][18])
#define OFF_CUR  (OFF_GI + 568*18)        // sCur [16][64]
#define SMEM_FLOATS (OFF_CUR + 16*64)
#define SMEM_BYTES  (SMEM_FLOATS * 4)

__device__ __forceinline__ void tr_slice(const float* src, float* dst, int O, int K,
                                         int start, int stride) {
    for (int i = start; i < O * K; i += stride) {
        int o = i / K, k = i - o * K;
        dst[k * O + o] = src[i];
    }
}

__global__ __launch_bounds__(THREADS, 1)
void rnn_kernel(const float* __restrict__ phys,
                const float* __restrict__ latents,
                const float* __restrict__ W_in, const float* __restrict__ b_in,
                const float* __restrict__ W_hp, const float* __restrict__ b_hp,
                const float* __restrict__ W_ih, const float* __restrict__ b_ih,
                const float* __restrict__ W_hh, const float* __restrict__ b_hh,
                const float* __restrict__ W_o1, const float* __restrict__ b_o1,
                const float* __restrict__ W_o2, const float* __restrict__ b_o2,
                float* __restrict__ out)
{
    extern __shared__ float sm[];
    float* sInT = sm + OFF_INT;
    float* sXT  = sm + OFF_XT;
    float* sHT  = sm + OFF_HT;
    float* sHCT = sm + OFF_HCT;
    float* sOT  = sm + OFF_OT;
    float* ghT  = sm + OFF_GH;
    float* giT  = sm + OFF_GI;
    float* sCur = sm + OFF_CUR;

    const int tid  = threadIdx.x;
    const int u    = tid & 127;        // thread within half-group
    const int rb   = (tid >> 7) * 8;   // row base: 0 or 8
    const int b0   = blockIdx.x * RT;

    // ---------- in-kernel weight transpose + grid barrier ----------
    {
        int start = blockIdx.x * THREADS + tid;
        int stride = NCTA * THREADS;
        tr_slice(W_in, g_WTin, NH, KIN, start, stride);
        tr_slice(W_hp, g_WThp, NH, NL, start, stride);
        tr_slice(W_ih, g_WTih, NH3, NH, start, stride);
        tr_slice(W_hh, g_WThh, NH3, NH, start, stride);
        tr_slice(W_o1, g_WTo1, NH, KO1, start, stride);
        tr_slice(W_o2, g_WTo2, NL, NH, start, stride);
    }
    __syncthreads();
    if (tid == 0) {
        unsigned p = g_rel;
        __threadfence();
        unsigned a = atomicAdd(&g_cnt, 1);
        if (a == NCTA - 1) {
            g_cnt = 0;
            __threadfence();
            g_rel = p + 1;
        } else {
            while (g_rel == p) { }
        }
        __threadfence();
    }
    __syncthreads();

    // ---------- prologue: cur = latents; sInT = [phys0 | cur]; h0 ----------
    for (int i = tid; i < RT * NL; i += THREADS) {
        int r = i & 15, l = i >> 4;
        float v = latents[(size_t)(b0 + r) * NL + l];
        sCur[r * NL + l] = v;
        sInT[(NP + l) * 20 + r] = v;
    }
    if (tid < RT * NP) {
        int r = tid >> 3, p = tid & 7;
        sInT[p * 20 + r] = phys[((size_t)(b0 + r) * NT + 0) * NP + p];
    }
    __syncthreads();
    if (tid < NH) {
        float acc[16];
#pragma unroll
        for (int r = 0; r < 16; r++) acc[r] = 0.0f;
        for (int k = 0; k < NL; k++) {
            float w = g_WThp[k * NH + tid];
#pragma unroll
            for (int r = 0; r < 16; r++)
                acc[r] = fmaf(sCur[r * NL + k], w, acc[r]);
        }
        float bb = b_hp[tid];
#pragma unroll
        for (int r = 0; r < 16; r++) sHT[tid * 20 + r] = acc[r] + bb;
    }
    __syncthreads();

    // ---------- main time loop ----------
#pragma unroll 1
    for (int t = 0; t < NT; t++) {
        // ===== Phase A: gh quad cols + (x pairs | gh tail) per half =====
        {
            u64 acc[4][4];
            gemm8<NH3, 4, 20>(sHT, rb, g_WThh, 4 * u, 0, NH, acc);
            float4 b4 = *reinterpret_cast<const float4*>(b_hh + 4 * u);
            const float* b4p = reinterpret_cast<const float*>(&b4);
#pragma unroll
            for (int c = 0; c < 4; c++) {
                u64 bp = dup2(b4p[c]);
                float* d = ghT + (4 * u + c) * 18 + rb;
#pragma unroll
                for (int rp = 0; rp < 4; rp++)
                    *reinterpret_cast<u64*>(d + 2 * rp) = ad2(acc[c][rp], bp);
            }
        }
        if (u < 90) {
            // x pairs: cols 2u, 2u+1 over K=72
            u64 acc[2][4];
            gemm8<NH, 2, 20>(sInT, rb, g_WTin, 2 * u, 0, KIN, acc);
#pragma unroll
            for (int c = 0; c < 2; c++) {
                float bb = b_in[2 * u + c];
                float* d = sXT + (2 * u + c) * 20 + rb;
#pragma unroll
                for (int rp = 0; rp < 4; rp++) {
                    float lo, hi;
                    unpk(acc[c][rp], lo, hi);
                    d[2 * rp]     = gelu_f(lo + bb);
                    d[2 * rp + 1] = gelu_f(hi + bb);
                }
            }
        } else if (u < 118) {
            // gh tail cols 512..539, full K
            int col = 512 + (u - 90);
            u64 acc[1][4];
            gemm8<NH3, 1, 20>(sHT, rb, g_WThh, col, 0, NH, acc);
            u64 bp = dup2(b_hh[col]);
            float* d = ghT + col * 18 + rb;
#pragma unroll
            for (int rp = 0; rp < 4; rp++)
                *reinterpret_cast<u64*>(d + 2 * rp) = ad2(acc[0][rp], bp);
        }
        __syncthreads();

        // ===== Phase B: gi quad cols + tail K-halves =====
        {
            u64 acc[4][4];
            gemm8<NH3, 4, 20>(sXT, rb, g_WTih, 4 * u, 0, NH, acc);
            float4 b4 = *reinterpret_cast<const float4*>(b_ih + 4 * u);
            const float* b4p = reinterpret_cast<const float*>(&b4);
#pragma unroll
            for (int c = 0; c < 4; c++) {
                u64 bp = dup2(b4p[c]);
                float* d = giT + (4 * u + c) * 18 + rb;
#pragma unroll
                for (int rp = 0; rp < 4; rp++)
                    *reinterpret_cast<u64*>(d + 2 * rp) = ad2(acc[c][rp], bp);
            }
        }
        if (u < 56) {
            // gi tail cols 512..539, K split [0,92) / [92,180)
            int s   = u >> 1;
            int seg = u & 1;
            int col = 512 + s;
            u64 acc[1][4];
            gemm8<NH3, 1, 20>(sXT, rb, g_WTih, col, seg ? 92 : 0, seg ? NH : 92, acc);
            if (seg == 0) {
                u64 bp = dup2(b_ih[col]);
                float* d = giT + col * 18 + rb;
#pragma unroll
                for (int rp = 0; rp < 4; rp++)
                    *reinterpret_cast<u64*>(d + 2 * rp) = ad2(acc[0][rp], bp);
            } else {
                float* d = giT + (540 + s) * 18 + rb;
#pragma unroll
                for (int rp = 0; rp < 4; rp++)
                    *reinterpret_cast<u64*>(d + 2 * rp) = acc[0][rp];
            }
        }
        __syncthreads();

        // ===== Phase C: gates -> h_new; build sHT, sHCT =====
        for (int i = tid; i < RT * NH; i += THREADS) {
            int r = i & 15, j = i >> 4;
            float gir = giT[j * 18 + r];
            float giz = giT[(NH + j) * 18 + r];
            float gin = giT[(2 * NH + j) * 18 + r];
            float ghr = ghT[j * 18 + r];
            float ghz = ghT[(NH + j) * 18 + r];
            float ghn = ghT[(2 * NH + j) * 18 + r];
            if (j >= 152) {
                int s = j - 152;
                gin += giT[(540 + s) * 18 + r];
            }
            float rr = sigmoid_f(gir + ghr);
            float zz = sigmoid_f(giz + ghz);
            float nn = tanhf(gin + rr * ghn);
            float hn = (1.0f - zz) * nn + zz * sHT[j * 20 + r];
            sHT[j * 20 + r]  = hn;
            sHCT[j * 20 + r] = hn;
        }
        for (int i = tid; i < RT * NL; i += THREADS) {
            int r = i & 15, l = i >> 4;
            sHCT[(NH + l) * 20 + r] = sCur[r * NL + l];
        }
        __syncthreads();

        // ===== Phase D: o1 partials — 360 jobs (180 cols x 2 K-segs) per half =====
#pragma unroll 1
        for (int wv = 0; wv < 3; wv++) {
            int j = u + 128 * wv;
            if (j < 360) {
                int seg = (j >= 180) ? 1 : 0;
                int col = j - 180 * seg;
                u64 acc[1][4];
                gemm8<NH, 1, 20>(sHCT, rb, g_WTo1, col, seg ? 124 : 0, seg ? KO1 : 124, acc);
                float* d = giT + (seg * 180 + col) * 18 + rb;
#pragma unroll
                for (int rp = 0; rp < 4; rp++)
                    *reinterpret_cast<u64*>(d + 2 * rp) = acc[0][rp];
            }
        }
        __syncthreads();

        // ===== Phase D2: reduce + bias + gelu -> sOT =====
        for (int i = tid; i < RT * NH; i += THREADS) {
            int r = i & 15, c = i >> 4;
            float v = giT[c * 18 + r] + giT[(180 + c) * 18 + r] + b_o1[c];
            sOT[c * 20 + r] = gelu_f(v);
        }
        __syncthreads();

        // ===== Phase E: o2 partials — 128 jobs (64 cols x 2 K-segs) per half =====
        {
            int col = u & 63;
            int seg = u >> 6;
            u64 acc[1][4];
            gemm8<NL, 1, 20>(sOT, rb, g_WTo2, col, seg ? 92 : 0, seg ? NH : 92, acc);
            float* d = ghT + (seg * 64 + col) * 18 + rb;
#pragma unroll
            for (int rp = 0; rp < 4; rp++)
                *reinterpret_cast<u64*>(d + 2 * rp) = acc[0][rp];
        }
        __syncthreads();

        // ===== Phase E2: reduce; cur update; write out; prep sInT =====
#pragma unroll
        for (int it = 0; it < 4; it++) {
            int i = tid + 256 * it;       // 0..1023
            int col = i & 63, r = i >> 6; // r 0..15
            float v = ghT[col * 18 + r] + ghT[(64 + col) * 18 + r] + b_o2[col];
            float c = sCur[r * NL + col] + v;
            c = fminf(fmaxf(c, 0.0f), 1.0f);
            sCur[r * NL + col] = c;
            sInT[(NP + col) * 20 + r] = c;
            out[((size_t)(b0 + r) * NT + t) * NL + col] = c;
        }
        if (tid < RT * NP && t + 1 < NT) {
            int r = tid >> 3, p = tid & 7;
            sInT[p * 20 + r] = phys[((size_t)(b0 + r) * NT + t + 1) * NP + p];
        }
        __syncthreads();
    }
}

extern "C" void kernel_launch(void* const* d_in, const int* in_sizes, int n_in,
                              void* d_out, int out_size)
{
    const float* phys    = (const float*)d_in[0];
    const float* latents = (const float*)d_in[1];
    const float* W_in    = (const float*)d_in[2];
    const float* b_in    = (const float*)d_in[3];
    const float* W_hp    = (const float*)d_in[4];
    const float* b_hp    = (const float*)d_in[5];
    const float* W_ih    = (const float*)d_in[6];
    const float* b_ih    = (const float*)d_in[7];
    const float* W_hh    = (const float*)d_in[8];
    const float* b_hh    = (const float*)d_in[9];
    const float* W_o1    = (const float*)d_in[10];
    const float* b_o1    = (const float*)d_in[11];
    const float* W_o2    = (const float*)d_in[12];
    const float* b_o2    = (const float*)d_in[13];
    float* out = (float*)d_out;

    cudaFuncSetAttribute(rnn_kernel,
                         cudaFuncAttributeMaxDynamicSharedMemorySize, SMEM_BYTES);
    rnn_kernel<<<NCTA, THREADS, SMEM_BYTES>>>(phys, latents,
                                              W_in, b_in, W_hp, b_hp,
                                              W_ih, b_ih, W_hh, b_hh,
                                              W_o1, b_o1, W_o2, b_o2, out);
}

// round 9
// speedup vs baseline: 1.3524x; 1.0075x over previous
#include <cuda_runtime.h>
#include <math.h>

// Problem dims
#define NB 2048
#define NT 512
#define NP 8
#define NL 64
#define NH 180
#define NH3 540
#define KIN (NP+NL)     // 72
#define KO1 (NH+NL)     // 244
#define KPAD 28

#define RT 8            // batch rows per CTA
#define NCTA (NB/RT)    // 256
#define THREADS 256
#define AST 12          // activation stride: 8 rows + pad
#define PST 10          // partial stride: 8 rows + pad (u64-aligned)

typedef unsigned long long u64;

// -------- K-major (transposed) weights, padded k-rows for deep prefetch ----
__device__ __align__(16) float g_WTin[(KIN+KPAD)*NH];
__device__ __align__(16) float g_WThp[(NL+KPAD)*NH];
__device__ __align__(16) float g_WTih[(NH+KPAD)*NH3];
__device__ __align__(16) float g_WThh[(NH+KPAD)*NH3];
__device__ __align__(16) float g_WTo1[(KO1+KPAD)*NH];
__device__ __align__(16) float g_WTo2[(NH+KPAD)*NL];

// grid barrier state
__device__ unsigned g_cnt = 0;
__device__ volatile unsigned g_rel = 0;

__device__ __forceinline__ u64 ff2(u64 a, u64 b, u64 c) {
    u64 d;
    asm("fma.rn.f32x2 %0, %1, %2, %3;" : "=l"(d) : "l"(a), "l"(b), "l"(c));
    return d;
}
__device__ __forceinline__ u64 ad2(u64 a, u64 b) {
    u64 d;
    asm("add.rn.f32x2 %0, %1, %2;" : "=l"(d) : "l"(a), "l"(b));
    return d;
}
__device__ __forceinline__ u64 dup2(float w) {
    u64 d;
    asm("mov.b64 %0, {%1, %1};" : "=l"(d) : "f"(w), "f"(w));
    return d;
}
__device__ __forceinline__ void unpk(u64 p, float& lo, float& hi) {
    asm("mov.b64 {%0, %1}, %2;" : "=f"(lo), "=f"(hi) : "l"(p));
}
__device__ __forceinline__ void fq(const float* p, u64& a, u64& b) {
    double2 q = *reinterpret_cast<const double2*>(p);
    a = __double_as_longlong(q.x);
    b = __double_as_longlong(q.y);
}
__device__ __forceinline__ float gelu_f(float x) {
    return 0.5f * x * (1.0f + erff(x * 0.7071067811865476f));
}
__device__ __forceinline__ float sigmoid_f(float x) {
    return 1.0f / (1.0f + expf(-x));
}

// ---- weight fetch: 4 k-rows x NC cols ----
template<int O, int NC>
__device__ __forceinline__ void lw(const float* Wc, int k, float (&w)[4][NC]) {
#pragma unroll
    for (int i = 0; i < 4; i++) {
        if constexpr (NC == 2) {
            float2 v = *reinterpret_cast<const float2*>(Wc + (size_t)(k + i) * O);
            w[i][0] = v.x; w[i][1] = v.y;
        } else {
            w[i][0] = Wc[(size_t)(k + i) * O];
        }
    }
}

// ---- compute chunk: 4 k's, NC cols, 8 rows (4 row-pairs) ----
template<int NC>
__device__ __forceinline__ void cc8(const float* sATk, const float (&w)[4][NC],
                                    u64 (&acc)[NC][4]) {
#pragma unroll
    for (int kk = 0; kk < 4; kk++) {
        u64 a[4];
        const float* ap = sATk + kk * AST;
        fq(ap,     a[0], a[1]);
        fq(ap + 4, a[2], a[3]);
#pragma unroll
        for (int c = 0; c < NC; c++) {
            u64 wp = dup2(w[kk][c]);
#pragma unroll
            for (int rp = 0; rp < 4; rp++)
                acc[c][rp] = ff2(a[rp], wp, acc[c][rp]);
        }
    }
}

// ---- pipelined GEMM: NC cols from col0, 8 rows, k in [k0,k1), (k1-k0)%4==0 ----
template<int O, int NC>
__device__ __forceinline__ void gemm8(const float* __restrict__ sAT,
                                      const float* __restrict__ W, int col0,
                                      int k0, int k1, u64 (&acc)[NC][4]) {
#pragma unroll
    for (int c = 0; c < NC; c++)
#pragma unroll
        for (int rp = 0; rp < 4; rp++) acc[c][rp] = 0ull;
    const float* Wc = W + col0;
    float w0[4][NC], w1[4][NC], w2[4][NC], w3[4][NC];
    lw<O, NC>(Wc, k0, w0);
    lw<O, NC>(Wc, k0 + 4, w1);
    lw<O, NC>(Wc, k0 + 8, w2);
    int k = k0;
#pragma unroll 1
    for (; k + 16 <= k1; k += 16) {
        lw<O, NC>(Wc, k + 12, w3); cc8<NC>(sAT + k * AST, w0, acc);
        lw<O, NC>(Wc, k + 16, w0); cc8<NC>(sAT + (k + 4) * AST, w1, acc);
        lw<O, NC>(Wc, k + 20, w1); cc8<NC>(sAT + (k + 8) * AST, w2, acc);
        lw<O, NC>(Wc, k + 24, w2); cc8<NC>(sAT + (k + 12) * AST, w3, acc);
    }
    if (k1 - k >= 4)  cc8<NC>(sAT + k * AST, w0, acc);
    if (k1 - k >= 8)  cc8<NC>(sAT + (k + 4) * AST, w1, acc);
    if (k1 - k >= 12) cc8<NC>(sAT + (k + 8) * AST, w2, acc);
}

// SMEM layout (floats)
#define OFF_INT  0                          // sInT [72][12]
#define OFF_XT   (OFF_INT + 72*AST)         // sXT  [180][12]
#define OFF_HT   (OFF_XT + 180*AST)         // sHT  [180][12]
#define OFF_HCT  (OFF_HT + 180*AST)         // sHCT [244][12]
#define OFF_OT   (OFF_HCT + 244*AST)        // sOT  [180][12]
#define OFF_GH   (OFF_OT + 180*AST)         // ghT  [568][10] (also o2 partials [256][10])
#define OFF_GI   (OFF_GH + 568*PST)         // giT  [720][10] (gi gates + o1 partials)
#define OFF_CUR  (OFF_GI + 720*PST)         // sCur [8][64]
#define SMEM_FLOATS (OFF_CUR + 8*64)
#define SMEM_BYTES  (SMEM_FLOATS * 4)

__device__ __forceinline__ void tr_slice(const float* src, float* dst, int O, int K,
                                         int start, int stride) {
    for (int i = start; i < O * K; i += stride) {
        int o = i / K, k = i - o * K;
        dst[k * O + o] = src[i];
    }
}

__global__ __launch_bounds__(THREADS, 2)
void rnn_kernel(const float* __restrict__ phys,
                const float* __restrict__ latents,
                const float* __restrict__ W_in, const float* __restrict__ b_in,
                const float* __restrict__ W_hp, const float* __restrict__ b_hp,
                const float* __restrict__ W_ih, const float* __restrict__ b_ih,
                const float* __restrict__ W_hh, const float* __restrict__ b_hh,
                const float* __restrict__ W_o1, const float* __restrict__ b_o1,
                const float* __restrict__ W_o2, const float* __restrict__ b_o2,
                float* __restrict__ out)
{
    extern __shared__ float sm[];
    float* sInT = sm + OFF_INT;
    float* sXT  = sm + OFF_XT;
    float* sHT  = sm + OFF_HT;
    float* sHCT = sm + OFF_HCT;
    float* sOT  = sm + OFF_OT;
    float* ghT  = sm + OFF_GH;
    float* giT  = sm + OFF_GI;
    float* sCur = sm + OFF_CUR;

    const int tid = threadIdx.x;
    const int b0  = blockIdx.x * RT;

    // ---------- in-kernel weight transpose + grid barrier ----------
    {
        int start = blockIdx.x * THREADS + tid;
        int stride = NCTA * THREADS;
        tr_slice(W_in, g_WTin, NH, KIN, start, stride);
        tr_slice(W_hp, g_WThp, NH, NL, start, stride);
        tr_slice(W_ih, g_WTih, NH3, NH, start, stride);
        tr_slice(W_hh, g_WThh, NH3, NH, start, stride);
        tr_slice(W_o1, g_WTo1, NH, KO1, start, stride);
        tr_slice(W_o2, g_WTo2, NL, NH, start, stride);
    }
    __syncthreads();
    if (tid == 0) {
        unsigned p = g_rel;
        __threadfence();
        unsigned a = atomicAdd(&g_cnt, 1);
        if (a == NCTA - 1) {
            g_cnt = 0;
            __threadfence();
            g_rel = p + 1;
        } else {
            while (g_rel == p) { }
        }
        __threadfence();
    }
    __syncthreads();

    // ---------- prologue: cur = latents; sInT = [phys0 | cur]; h0 ----------
    for (int i = tid; i < RT * NL; i += THREADS) {
        int r = i & 7, l = i >> 3;
        float v = latents[(size_t)(b0 + r) * NL + l];
        sCur[r * NL + l] = v;
        sInT[(NP + l) * AST + r] = v;
    }
    if (tid < RT * NP) {
        int r = tid >> 3, p = tid & 7;
        sInT[p * AST + r] = phys[((size_t)(b0 + r) * NT + 0) * NP + p];
    }
    __syncthreads();
    if (tid < NH) {
        float acc[8];
#pragma unroll
        for (int r = 0; r < 8; r++) acc[r] = 0.0f;
        for (int k = 0; k < NL; k++) {
            float w = g_WThp[k * NH + tid];
#pragma unroll
            for (int r = 0; r < 8; r++)
                acc[r] = fmaf(sCur[r * NL + k], w, acc[r]);
        }
        float bb = b_hp[tid];
#pragma unroll
        for (int r = 0; r < 8; r++) sHT[tid * AST + r] = acc[r] + bb;
    }
    __syncthreads();

    // ---------- main time loop ----------
#pragma unroll 1
    for (int t = 0; t < NT; t++) {
        // ===== Phase A: gh main (2 cols/thread) + x (cols 0..179) + gh tail halves =====
        {
            u64 acc[2][4];
            gemm8<NH3, 2>(sHT, g_WThh, 2 * tid, 0, NH, acc);
            float2 b2 = *reinterpret_cast<const float2*>(b_hh + 2 * tid);
#pragma unroll
            for (int c = 0; c < 2; c++) {
                u64 bp = dup2(c ? b2.y : b2.x);
                float* d = ghT + (2 * tid + c) * PST;
#pragma unroll
                for (int rp = 0; rp < 4; rp++)
                    *reinterpret_cast<u64*>(d + 2 * rp) = ad2(acc[c][rp], bp);
            }
        }
        if (tid < 180) {
            // x col = tid, K=72
            u64 acc[1][4];
            gemm8<NH, 1>(sInT, g_WTin, tid, 0, KIN, acc);
            float bb = b_in[tid];
            float* d = sXT + tid * AST;
#pragma unroll
            for (int rp = 0; rp < 4; rp++) {
                float lo, hi;
                unpk(acc[0][rp], lo, hi);
                d[2 * rp]     = gelu_f(lo + bb);
                d[2 * rp + 1] = gelu_f(hi + bb);
            }
        } else if (tid < 236) {
            // gh tail cols 512..539, K halves [0,92)/[92,180)
            int idx = tid - 180;
            int s = idx >> 1, seg = idx & 1;
            int col = 512 + s;
            u64 acc[1][4];
            gemm8<NH3, 1>(sHT, g_WThh, col, seg ? 92 : 0, seg ? NH : 92, acc);
            if (seg == 0) {
                u64 bp = dup2(b_hh[col]);
                float* d = ghT + col * PST;
#pragma unroll
                for (int rp = 0; rp < 4; rp++)
                    *reinterpret_cast<u64*>(d + 2 * rp) = ad2(acc[0][rp], bp);
            } else {
                float* d = ghT + (540 + s) * PST;
#pragma unroll
                for (int rp = 0; rp < 4; rp++)
                    *reinterpret_cast<u64*>(d + 2 * rp) = acc[0][rp];
            }
        }
        __syncthreads();

        // ===== Phase B: gi main (2 cols/thread) + tail halves on threads 0..55 =====
        {
            u64 acc[2][4];
            gemm8<NH3, 2>(sXT, g_WTih, 2 * tid, 0, NH, acc);
            float2 b2 = *reinterpret_cast<const float2*>(b_ih + 2 * tid);
#pragma unroll
            for (int c = 0; c < 2; c++) {
                u64 bp = dup2(c ? b2.y : b2.x);
                float* d = giT + (2 * tid + c) * PST;
#pragma unroll
                for (int rp = 0; rp < 4; rp++)
                    *reinterpret_cast<u64*>(d + 2 * rp) = ad2(acc[c][rp], bp);
            }
        }
        if (tid < 56) {
            int s = tid >> 1, seg = tid & 1;
            int col = 512 + s;
            u64 acc[1][4];
            gemm8<NH3, 1>(sXT, g_WTih, col, seg ? 92 : 0, seg ? NH : 92, acc);
            if (seg == 0) {
                u64 bp = dup2(b_ih[col]);
                float* d = giT + col * PST;
#pragma unroll
                for (int rp = 0; rp < 4; rp++)
                    *reinterpret_cast<u64*>(d + 2 * rp) = ad2(acc[0][rp], bp);
            } else {
                float* d = giT + (540 + s) * PST;
#pragma unroll
                for (int rp = 0; rp < 4; rp++)
                    *reinterpret_cast<u64*>(d + 2 * rp) = acc[0][rp];
            }
        }
        __syncthreads();

        // ===== Phase C: gates -> h_new; build sHT, sHCT =====
        for (int i = tid; i < RT * NH; i += THREADS) {
            int r = i & 7, j = i >> 3;
            float gir = giT[j * PST + r];
            float giz = giT[(NH + j) * PST + r];
            float gin = giT[(2 * NH + j) * PST + r];
            float ghr = ghT[j * PST + r];
            float ghz = ghT[(NH + j) * PST + r];
            float ghn = ghT[(2 * NH + j) * PST + r];
            if (j >= 152) {
                int s = j - 152;
                gin += giT[(540 + s) * PST + r];
                ghn += ghT[(540 + s) * PST + r];
            }
            float rr = sigmoid_f(gir + ghr);
            float zz = sigmoid_f(giz + ghz);
            float nn = tanhf(gin + rr * ghn);
            float hn = (1.0f - zz) * nn + zz * sHT[j * AST + r];
            sHT[j * AST + r]  = hn;
            sHCT[j * AST + r] = hn;
        }
        for (int i = tid; i < RT * NL; i += THREADS) {
            int r = i & 7, l = i >> 3;
            sHCT[(NH + l) * AST + r] = sCur[r * NL + l];
        }
        __syncthreads();

        // ===== Phase D: o1 partials — 720 jobs (180 cols x 4 K-quarters) =====
        {
            static const int dk0[4] = { 0, 64, 124, 184 };
            static const int dk1[4] = { 64, 124, 184, 244 };
#pragma unroll 1
            for (int j = tid; j < 720; j += THREADS) {
                int q = j / 180;
                int col = j - 180 * q;
                u64 acc[1][4];
                gemm8<NH, 1>(sHCT, g_WTo1, col, dk0[q], dk1[q], acc);
                float* d = giT + j * PST;
#pragma unroll
                for (int rp = 0; rp < 4; rp++)
                    *reinterpret_cast<u64*>(d + 2 * rp) = acc[0][rp];
            }
        }
        __syncthreads();

        // ===== Phase D2: reduce + bias + gelu -> sOT =====
        for (int i = tid; i < RT * NH; i += THREADS) {
            int r = i & 7, c = i >> 3;
            float v = giT[c * PST + r] + giT[(180 + c) * PST + r]
                    + giT[(360 + c) * PST + r] + giT[(540 + c) * PST + r]
                    + b_o1[c];
            sOT[c * AST + r] = gelu_f(v);
        }
        __syncthreads();

        // ===== Phase E: o2 partials — exactly 256 jobs (64 cols x 4 K-quarters) =====
        {
            static const int ek0[4] = { 0, 48, 92, 136 };
            static const int ek1[4] = { 48, 92, 136, 180 };
            int col = tid & 63;
            int q = tid >> 6;
            u64 acc[1][4];
            gemm8<NL, 1>(sOT, g_WTo2, col, ek0[q], ek1[q], acc);
            float* d = ghT + tid * PST;
#pragma unroll
            for (int rp = 0; rp < 4; rp++)
                *reinterpret_cast<u64*>(d + 2 * rp) = acc[0][rp];
        }
        __syncthreads();

        // ===== Phase E2: reduce; cur update; write out; prep sInT =====
#pragma unroll
        for (int it = 0; it < 2; it++) {
            int i = tid + 256 * it;       // 0..511
            int col = i & 63, r = i >> 6; // r 0..7
            float v = ghT[col * PST + r] + ghT[(64 + col) * PST + r]
                    + ghT[(128 + col) * PST + r] + ghT[(192 + col) * PST + r]
                    + b_o2[col];
            float c = sCur[r * NL + col] + v;
            c = fminf(fmaxf(c, 0.0f), 1.0f);
            sCur[r * NL + col] = c;
            sInT[(NP + col) * AST + r] = c;
            out[((size_t)(b0 + r) * NT + t) * NL + col] = c;
        }
        if (tid < RT * NP && t + 1 < NT) {
            int r = tid >> 3, p = tid & 7;
            sInT[p * AST + r] = phys[((size_t)(b0 + r) * NT + t + 1) * NP + p];
        }
        __syncthreads();
    }
}

extern "C" void kernel_launch(void* const* d_in, const int* in_sizes, int n_in,
                              void* d_out, int out_size)
{
    const float* phys    = (const float*)d_in[0];
    const float* latents = (const float*)d_in[1];
    const float* W_in    = (const float*)d_in[2];
    const float* b_in    = (const float*)d_in[3];
    const float* W_hp    = (const float*)d_in[4];
    const float* b_hp    = (const float*)d_in[5];
    const float* W_ih    = (const float*)d_in[6];
    const float* b_ih    = (const float*)d_in[7];
    const float* W_hh    = (const float*)d_in[8];
    const float* b_hh    = (const float*)d_in[9];
    const float* W_o1    = (const float*)d_in[10];
    const float* b_o1    = (const float*)d_in[11];
    const float* W_o2    = (const float*)d_in[12];
    const float* b_o2    = (const float*)d_in[13];
    float* out = (float*)d_out;

    cudaFuncSetAttribute(rnn_kernel,
                         cudaFuncAttributeMaxDynamicSharedMemorySize, SMEM_BYTES);
    rnn_kernel<<<NCTA, THREADS, SMEM_BYTES>>>(phys, latents,
                                              W_in, b_in, W_hp, b_hp,
                                              W_ih, b_ih, W_hh, b_hh,
                                              W_o1, b_o1, W_o2, b_o2, out);
}